// round 4
// baseline (speedup 1.0000x reference)
#include <cuda_runtime.h>
#include <math.h>

#define N_NODES 10000
#define N_EDGES 160000
#define H       128
#define F3H     384
#define E_RBF   20
#define L_LAYERS 3
#define PI_F    3.14159265358979f
#define CUTOFF_F 5.0f

#define NPB  8    // nodes per block (scalar_out / readout)
#define NPU  4    // nodes per block (update) — proven R1 config
#define EPB  32   // edges per block (edge kernel, warp-per-edge)

// ---------- persistent scratch ----------
__device__ float g_ns  [N_NODES * H];
__device__ float g_vecA[N_NODES * 3 * H];
__device__ float g_vecB[N_NODES * 3 * H];
__device__ float g_so  [N_NODES * F3H];

__device__ __forceinline__ float silu_f(float x) {
    return x / (1.0f + expf(-x));
}

__device__ __forceinline__ float4 f4_fma(float4 a, float s, float4 acc) {
    acc.x += a.x * s; acc.y += a.y * s; acc.z += a.z * s; acc.w += a.w * s;
    return acc;
}

// ---------- init ----------
__global__ void __launch_bounds__(H) k_init(const int* __restrict__ z,
                                            const float* __restrict__ embed) {
    int i = blockIdx.x, j = threadIdx.x;
    g_ns[i * H + j] = embed[z[i] * H + j];
#pragma unroll
    for (int d = 0; d < 3; d++) g_vecA[i * 3 * H + d * H + j] = 0.0f;
}

// ---------- vecB = vecA ----------
__global__ void k_copy_vec() {
    int idx = blockIdx.x * blockDim.x + threadIdx.x;
    const float4* src = reinterpret_cast<const float4*>(g_vecA);
    float4* dst = reinterpret_cast<float4*>(g_vecB);
    if (idx < N_NODES * 3 * H / 4) dst[idx] = src[idx];
}

// ---------- scalar_out = silu(ns @ W1 + b1) @ W2 + b2 ----------
__global__ void __launch_bounds__(H) k_scalar_out(const float* __restrict__ W1,
                                                  const float* __restrict__ b1,
                                                  const float* __restrict__ W2,
                                                  const float* __restrict__ b2) {
    int i0 = blockIdx.x * NPB, j = threadIdx.x;
    __shared__ float s_x[NPB][H];
    __shared__ float s_h[NPB][H];
#pragma unroll
    for (int n = 0; n < NPB; n++) s_x[n][j] = g_ns[(i0 + n) * H + j];
    __syncthreads();

    float acc[NPB];
    float bb = b1[j];
#pragma unroll
    for (int n = 0; n < NPB; n++) acc[n] = bb;
    for (int k = 0; k < H; k++) {
        float w = W1[k * H + j];
#pragma unroll
        for (int n = 0; n < NPB; n++) acc[n] += s_x[n][k] * w;
    }
#pragma unroll
    for (int n = 0; n < NPB; n++) s_h[n][j] = silu_f(acc[n]);
    __syncthreads();

    float a0[NPB], a1[NPB], a2[NPB];
    float c0 = b2[j], c1 = b2[H + j], c2 = b2[2 * H + j];
#pragma unroll
    for (int n = 0; n < NPB; n++) { a0[n] = c0; a1[n] = c1; a2[n] = c2; }
    for (int k = 0; k < H; k++) {
        float w0 = W2[k * F3H + j];
        float w1 = W2[k * F3H + H + j];
        float w2 = W2[k * F3H + 2 * H + j];
#pragma unroll
        for (int n = 0; n < NPB; n++) {
            float h = s_h[n][k];
            a0[n] += h * w0; a1[n] += h * w1; a2[n] += h * w2;
        }
    }
#pragma unroll
    for (int n = 0; n < NPB; n++) {
        g_so[(i0 + n) * F3H + j]         = a0[n];
        g_so[(i0 + n) * F3H + H + j]     = a1[n];
        g_so[(i0 + n) * F3H + 2 * H + j] = a2[n];
    }
}

// ---------- edge kernel: warp-per-edge, float4 lanes, float4 atomics ----------
__global__ void __launch_bounds__(256, 4) k_edge(const int* __restrict__ edge,
                                                 const float* __restrict__ ediff,
                                                 const float* __restrict__ edist,
                                                 const float* __restrict__ Fw,
                                                 const float* __restrict__ Fb) {
    int tid = threadIdx.x;
    int warp = tid >> 5, lane = tid & 31;
    int e0 = blockIdx.x * EPB;

    __shared__ alignas(16) float s_Fw[E_RBF * F3H];   // 30 KB
    __shared__ alignas(16) float s_Fb[F3H];
    __shared__ float s_rbf[EPB][E_RBF];
    __shared__ float s_unit[EPB][3];
    __shared__ float s_fcut[EPB];
    __shared__ int   s_sd[EPB][2];

    for (int t = tid; t < E_RBF * F3H / 4; t += 256)
        reinterpret_cast<float4*>(s_Fw)[t] = reinterpret_cast<const float4*>(Fw)[t];
    for (int t = tid; t < F3H; t += 256) s_Fb[t] = Fb[t];

    for (int t = tid; t < EPB * E_RBF; t += 256) {
        int ee = t / E_RBF, k = t % E_RBF;
        float dist = edist[e0 + ee];
        s_rbf[ee][k] = sinf(dist * (float)(k + 1) * (PI_F / CUTOFF_F)) / dist;
    }
    if (tid < EPB) {
        int e = e0 + tid;
        float dist = edist[e];
        s_fcut[tid] = (dist < CUTOFF_F) ? 0.5f * (cosf(PI_F * dist / CUTOFF_F) + 1.0f) : 0.0f;
        float inv = 1.0f / dist;
        s_unit[tid][0] = ediff[3 * e + 0] * inv;
        s_unit[tid][1] = ediff[3 * e + 1] * inv;
        s_unit[tid][2] = ediff[3 * e + 2] * inv;
        s_sd[tid][0] = edge[2 * e];       // dst
        s_sd[tid][1] = edge[2 * e + 1];   // src
    }
    __syncthreads();

    int c = lane * 4;   // this lane's 4 columns
    for (int ee = warp; ee < EPB; ee += 8) {
        int dst = s_sd[ee][0], src = s_sd[ee][1];
        float fcut = s_fcut[ee];
        float ux = s_unit[ee][0], uy = s_unit[ee][1], uz = s_unit[ee][2];

        float4 fw0 = *reinterpret_cast<const float4*>(&s_Fb[c]);
        float4 fw1 = *reinterpret_cast<const float4*>(&s_Fb[H + c]);
        float4 fw2 = *reinterpret_cast<const float4*>(&s_Fb[2 * H + c]);
#pragma unroll
        for (int k = 0; k < E_RBF; k++) {
            float r = s_rbf[ee][k];
            const float* row = s_Fw + k * F3H;
            fw0 = f4_fma(*reinterpret_cast<const float4*>(row + c), r, fw0);
            fw1 = f4_fma(*reinterpret_cast<const float4*>(row + H + c), r, fw1);
            fw2 = f4_fma(*reinterpret_cast<const float4*>(row + 2 * H + c), r, fw2);
        }

        const float4* so = reinterpret_cast<const float4*>(g_so + (size_t)src * F3H);
        float4 so0 = so[lane], so1 = so[32 + lane], so2 = so[64 + lane];

        float4 gsv, gev, ms;
        gsv.x = fw0.x * fcut * so0.x; gsv.y = fw0.y * fcut * so0.y;
        gsv.z = fw0.z * fcut * so0.z; gsv.w = fw0.w * fcut * so0.w;
        gev.x = fw1.x * fcut * so1.x; gev.y = fw1.y * fcut * so1.y;
        gev.z = fw1.z * fcut * so1.z; gev.w = fw1.w * fcut * so1.w;
        ms.x  = fw2.x * fcut * so2.x; ms.y  = fw2.y * fcut * so2.y;
        ms.z  = fw2.z * fcut * so2.z; ms.w  = fw2.w * fcut * so2.w;

        atomicAdd(reinterpret_cast<float4*>(&g_ns[(size_t)dst * H + c]), ms);

        const float4* vin = reinterpret_cast<const float4*>(g_vecA + (size_t)src * 3 * H);
        float4* vout = reinterpret_cast<float4*>(g_vecB + (size_t)dst * 3 * H);
        float u[3] = {ux, uy, uz};
#pragma unroll
        for (int d = 0; d < 3; d++) {
            float4 v = vin[d * 32 + lane];
            float4 mv;
            mv.x = v.x * gsv.x + gev.x * u[d];
            mv.y = v.y * gsv.y + gev.y * u[d];
            mv.z = v.z * gsv.z + gev.z * u[d];
            mv.w = v.w * gsv.w + gev.w * u[d];
            atomicAdd(&vout[d * 32 + lane], mv);
        }
    }
}

// ---------- update block (R1 config, NPU=4) ----------
__global__ void __launch_bounds__(H) k_update(const float* __restrict__ Uw,
                                              const float* __restrict__ Ub,
                                              const float* __restrict__ Vw,
                                              const float* __restrict__ Vb,
                                              const float* __restrict__ W1,
                                              const float* __restrict__ b1,
                                              const float* __restrict__ W2,
                                              const float* __restrict__ b2) {
    int i0 = blockIdx.x * NPU, j = threadIdx.x;
    __shared__ float s_v[NPU][3 * H];
    __shared__ float s_in[NPU][2 * H];
    __shared__ float s_h[NPU][H];

    float ns[NPU];
#pragma unroll
    for (int n = 0; n < NPU; n++) {
#pragma unroll
        for (int d = 0; d < 3; d++)
            s_v[n][d * H + j] = g_vecB[(i0 + n) * 3 * H + d * H + j];
        ns[n] = g_ns[(i0 + n) * H + j];
        s_in[n][H + j] = ns[n];
    }
    __syncthreads();

    float Uv[NPU][3], Vv[NPU][3];
    float ub = Ub[j], vb = Vb[j];
#pragma unroll
    for (int n = 0; n < NPU; n++)
#pragma unroll
        for (int d = 0; d < 3; d++) { Uv[n][d] = ub; Vv[n][d] = vb; }

    for (int k = 0; k < H; k++) {
        float u = Uw[k * H + j];
        float v = Vw[k * H + j];
#pragma unroll
        for (int n = 0; n < NPU; n++)
#pragma unroll
            for (int d = 0; d < 3; d++) {
                float x = s_v[n][d * H + k];
                Uv[n][d] += x * u;
                Vv[n][d] += x * v;
            }
    }
#pragma unroll
    for (int n = 0; n < NPU; n++)
        s_in[n][j] = sqrtf(Vv[n][0] * Vv[n][0] + Vv[n][1] * Vv[n][1] + Vv[n][2] * Vv[n][2]);
    __syncthreads();

    float acc[NPU];
    float bb = b1[j];
#pragma unroll
    for (int n = 0; n < NPU; n++) acc[n] = bb;
    for (int k = 0; k < 2 * H; k++) {
        float w = W1[k * H + j];
#pragma unroll
        for (int n = 0; n < NPU; n++) acc[n] += s_in[n][k] * w;
    }
#pragma unroll
    for (int n = 0; n < NPU; n++) s_h[n][j] = silu_f(acc[n]);
    __syncthreads();

    float a0[NPU], a1[NPU], a2[NPU];
    float c0 = b2[j], c1 = b2[H + j], c2 = b2[2 * H + j];
#pragma unroll
    for (int n = 0; n < NPU; n++) { a0[n] = c0; a1[n] = c1; a2[n] = c2; }
    for (int k = 0; k < H; k++) {
        float w0 = W2[k * F3H + j];
        float w1 = W2[k * F3H + H + j];
        float w2 = W2[k * F3H + 2 * H + j];
#pragma unroll
        for (int n = 0; n < NPU; n++) {
            float h = s_h[n][k];
            a0[n] += h * w0; a1[n] += h * w1; a2[n] += h * w2;
        }
    }
#pragma unroll
    for (int n = 0; n < NPU; n++) {
        float dot = 0.0f;
#pragma unroll
        for (int d = 0; d < 3; d++) {
            g_vecA[(i0 + n) * 3 * H + d * H + j] = s_v[n][d * H + j] + a0[n] * Uv[n][d];
            dot += Uv[n][d] * Vv[n][d];
        }
        g_ns[(i0 + n) * H + j] = ns[n] + a1[n] * dot + a2[n];
    }
}

// ---------- readout ----------
__global__ void __launch_bounds__(H) k_readout(const float* __restrict__ W1,
                                               const float* __restrict__ b1,
                                               const float* __restrict__ W2,
                                               const float* __restrict__ b2,
                                               float* __restrict__ out) {
    int i0 = blockIdx.x * NPB, j = threadIdx.x;
    __shared__ float s_x[NPB][H];
    __shared__ float s_h[NPB][H];
#pragma unroll
    for (int n = 0; n < NPB; n++) s_x[n][j] = g_ns[(i0 + n) * H + j];
    __syncthreads();

    float acc[NPB];
    float bb = b1[j];
#pragma unroll
    for (int n = 0; n < NPB; n++) acc[n] = bb;
    for (int k = 0; k < H; k++) {
        float w = W1[k * H + j];
#pragma unroll
        for (int n = 0; n < NPB; n++) acc[n] += s_x[n][k] * w;
    }
#pragma unroll
    for (int n = 0; n < NPB; n++) s_h[n][j] = silu_f(acc[n]);
    __syncthreads();

    float a[NPB];
    float c = b2[j];
#pragma unroll
    for (int n = 0; n < NPB; n++) a[n] = c;
    for (int k = 0; k < H; k++) {
        float w = W2[k * H + j];
#pragma unroll
        for (int n = 0; n < NPB; n++) a[n] += s_h[n][k] * w;
    }
#pragma unroll
    for (int n = 0; n < NPB; n++) out[(i0 + n) * H + j] = a[n];
}

// ---------- host launcher ----------
extern "C" void kernel_launch(void* const* d_in, const int* in_sizes, int n_in,
                              void* d_out, int out_size) {
    const int*   z      = (const int*)  d_in[0];
    const int*   edge   = (const int*)  d_in[1];
    const float* ediff  = (const float*)d_in[2];
    const float* edist  = (const float*)d_in[3];
    const float* embed  = (const float*)d_in[4];
    const float* mfw    = (const float*)d_in[5];
    const float* mfb    = (const float*)d_in[6];
    const float* mw1    = (const float*)d_in[7];
    const float* mb1    = (const float*)d_in[8];
    const float* mw2    = (const float*)d_in[9];
    const float* mb2    = (const float*)d_in[10];
    const float* uUw    = (const float*)d_in[11];
    const float* uUb    = (const float*)d_in[12];
    const float* uVw    = (const float*)d_in[13];
    const float* uVb    = (const float*)d_in[14];
    const float* uw1    = (const float*)d_in[15];
    const float* ub1    = (const float*)d_in[16];
    const float* uw2    = (const float*)d_in[17];
    const float* ub2    = (const float*)d_in[18];
    const float* row1   = (const float*)d_in[19];
    const float* rob1   = (const float*)d_in[20];
    const float* row2   = (const float*)d_in[21];
    const float* rob2   = (const float*)d_in[22];
    float* out = (float*)d_out;

    k_init<<<N_NODES, H>>>(z, embed);

    int copy_threads = N_NODES * 3 * H / 4;
    for (int l = 0; l < L_LAYERS; l++) {
        k_scalar_out<<<N_NODES / NPB, H>>>(mw1 + l * H * H, mb1 + l * H,
                                           mw2 + l * H * F3H, mb2 + l * F3H);
        k_copy_vec<<<(copy_threads + 255) / 256, 256>>>();
        k_edge<<<N_EDGES / EPB, 256>>>(edge, ediff, edist,
                                       mfw + l * E_RBF * F3H, mfb + l * F3H);
        k_update<<<N_NODES / NPU, H>>>(uUw + l * H * H, uUb + l * H,
                                       uVw + l * H * H, uVb + l * H,
                                       uw1 + l * 2 * H * H, ub1 + l * H,
                                       uw2 + l * H * F3H, ub2 + l * F3H);
    }
    k_readout<<<N_NODES / NPB, H>>>(row1, rob1, row2, rob2, out);
}

// round 5
// speedup vs baseline: 2.5794x; 2.5794x over previous
#include <cuda_runtime.h>
#include <math.h>

#define N_NODES 10000
#define N_EDGES 160000
#define H       128
#define F3H     384
#define E_RBF   20
#define L_LAYERS 3
#define PI_F    3.14159265358979f
#define CUTOFF_F 5.0f

#define NPB 4     // nodes per block (scalar_out / readout) — proven R1
#define NPU 4     // nodes per block (update) — proven R1
#define NGB 4     // nodes per block (aggregate)

// ---------- persistent scratch ----------
__device__ float g_ns  [N_NODES * H];        // node_scalar (post-update)
__device__ float g_ns2 [N_NODES * H];        // node_scalar (post-aggregation)
__device__ float g_vecA[N_NODES * 3 * H];    // node_vector (post-update)
__device__ float g_vecB[N_NODES * 3 * H];    // node_vector (post-aggregation)
__device__ float g_so  [N_NODES * F3H];      // scalar_out

// CSR / sorted edge data (built once per launch)
__device__ int   g_rowptr[N_NODES + 1];
__device__ int   g_cursor[N_NODES];
__device__ int   g_src_s [N_EDGES];          // src node, dst-sorted
__device__ float g_fcut_s[N_EDGES];
__device__ float g_unit_s[N_EDGES * 3];
__device__ float g_rbf_s [N_EDGES * E_RBF];

__device__ __forceinline__ float silu_f(float x) {
    return x / (1.0f + expf(-x));
}

// ---------- CSR build ----------
__global__ void k_zero_cnt() {
    int i = blockIdx.x * blockDim.x + threadIdx.x;
    if (i < N_NODES) g_cursor[i] = 0;
}

__global__ void k_hist(const int* __restrict__ edge) {
    int e = blockIdx.x * blockDim.x + threadIdx.x;
    if (e < N_EDGES) atomicAdd(&g_cursor[edge[2 * e]], 1);
}

__global__ void __launch_bounds__(1024) k_scan() {
    __shared__ int s_part[1024];
    int tid = threadIdx.x;
    const int CH = 10;                  // 1024*10 >= 10000
    int base = tid * CH;
    int local[CH];
    int sum = 0;
#pragma unroll
    for (int i = 0; i < CH; i++) {
        int idx = base + i;
        int v = (idx < N_NODES) ? g_cursor[idx] : 0;
        local[i] = sum;
        sum += v;
    }
    s_part[tid] = sum;
    __syncthreads();
    for (int off = 1; off < 1024; off <<= 1) {
        int add = (tid >= off) ? s_part[tid - off] : 0;
        __syncthreads();
        s_part[tid] += add;
        __syncthreads();
    }
    int excl = (tid > 0) ? s_part[tid - 1] : 0;
#pragma unroll
    for (int i = 0; i < CH; i++) {
        int idx = base + i;
        if (idx < N_NODES) {
            int rp = excl + local[i];
            g_rowptr[idx] = rp;
            g_cursor[idx] = rp;
        }
    }
    if (tid == 0) g_rowptr[N_NODES] = N_EDGES;
}

// scatter edges into dst-sorted order + precompute rbf/fcut/unit (layer-invariant)
__global__ void k_scatter(const int* __restrict__ edge,
                          const float* __restrict__ ediff,
                          const float* __restrict__ edist) {
    int e = blockIdx.x * blockDim.x + threadIdx.x;
    if (e >= N_EDGES) return;
    int dst = edge[2 * e], src = edge[2 * e + 1];
    int pos = atomicAdd(&g_cursor[dst], 1);
    g_src_s[pos] = src;
    float dist = edist[e];
    g_fcut_s[pos] = (dist < CUTOFF_F) ? 0.5f * (cosf(PI_F * dist / CUTOFF_F) + 1.0f) : 0.0f;
    float inv = 1.0f / dist;
    g_unit_s[3 * pos + 0] = ediff[3 * e + 0] * inv;
    g_unit_s[3 * pos + 1] = ediff[3 * e + 1] * inv;
    g_unit_s[3 * pos + 2] = ediff[3 * e + 2] * inv;
#pragma unroll
    for (int k = 0; k < E_RBF; k++)
        g_rbf_s[pos * E_RBF + k] = sinf(dist * (float)(k + 1) * (PI_F / CUTOFF_F)) * inv;
}

// ---------- init ----------
__global__ void __launch_bounds__(H) k_init(const int* __restrict__ z,
                                            const float* __restrict__ embed) {
    int i = blockIdx.x, j = threadIdx.x;
    g_ns[i * H + j] = embed[z[i] * H + j];
#pragma unroll
    for (int d = 0; d < 3; d++) g_vecA[i * 3 * H + d * H + j] = 0.0f;
}

// ---------- scalar_out = silu(ns @ W1 + b1) @ W2 + b2 ----------
__global__ void __launch_bounds__(H) k_scalar_out(const float* __restrict__ W1,
                                                  const float* __restrict__ b1,
                                                  const float* __restrict__ W2,
                                                  const float* __restrict__ b2) {
    int i0 = blockIdx.x * NPB, j = threadIdx.x;
    __shared__ float s_x[NPB][H];
    __shared__ float s_h[NPB][H];
#pragma unroll
    for (int n = 0; n < NPB; n++) s_x[n][j] = g_ns[(i0 + n) * H + j];
    __syncthreads();

    float acc[NPB];
    float bb = b1[j];
#pragma unroll
    for (int n = 0; n < NPB; n++) acc[n] = bb;
    for (int k = 0; k < H; k++) {
        float w = W1[k * H + j];
#pragma unroll
        for (int n = 0; n < NPB; n++) acc[n] += s_x[n][k] * w;
    }
#pragma unroll
    for (int n = 0; n < NPB; n++) s_h[n][j] = silu_f(acc[n]);
    __syncthreads();

    float a0[NPB], a1[NPB], a2[NPB];
    float c0 = b2[j], c1 = b2[H + j], c2 = b2[2 * H + j];
#pragma unroll
    for (int n = 0; n < NPB; n++) { a0[n] = c0; a1[n] = c1; a2[n] = c2; }
    for (int k = 0; k < H; k++) {
        float w0 = W2[k * F3H + j];
        float w1 = W2[k * F3H + H + j];
        float w2 = W2[k * F3H + 2 * H + j];
#pragma unroll
        for (int n = 0; n < NPB; n++) {
            float h = s_h[n][k];
            a0[n] += h * w0; a1[n] += h * w1; a2[n] += h * w2;
        }
    }
#pragma unroll
    for (int n = 0; n < NPB; n++) {
        g_so[(i0 + n) * F3H + j]         = a0[n];
        g_so[(i0 + n) * F3H + H + j]     = a1[n];
        g_so[(i0 + n) * F3H + 2 * H + j] = a2[n];
    }
}

// ---------- aggregate: per-dst gather, NO atomics ----------
// writes: g_ns2 = g_ns + sum(msg_s), g_vecB = g_vecA + sum(msg_v)
__global__ void __launch_bounds__(H) k_aggregate(const float* __restrict__ Fw,
                                                 const float* __restrict__ Fb) {
    int j = threadIdx.x;
    __shared__ alignas(16) float s_Fw[E_RBF * F3H];  // 30 KB
    __shared__ float s_Fb[F3H];
    for (int t = j; t < E_RBF * F3H / 4; t += H)
        reinterpret_cast<float4*>(s_Fw)[t] = reinterpret_cast<const float4*>(Fw)[t];
    for (int t = j; t < F3H; t += H) s_Fb[t] = Fb[t];
    __syncthreads();

    int n0 = blockIdx.x * NGB;
    for (int n = n0; n < n0 + NGB; n++) {
        int r0 = g_rowptr[n], r1 = g_rowptr[n + 1];
        float accs = 0.0f, av0 = 0.0f, av1 = 0.0f, av2 = 0.0f;
        for (int p = r0; p < r1; p++) {
            int src = g_src_s[p];
            float fcut = g_fcut_s[p];
            float u0 = g_unit_s[3 * p + 0];
            float u1 = g_unit_s[3 * p + 1];
            float u2 = g_unit_s[3 * p + 2];

            float fw0 = s_Fb[j], fw1 = s_Fb[H + j], fw2 = s_Fb[2 * H + j];
            const float* rbf = g_rbf_s + p * E_RBF;
#pragma unroll
            for (int k = 0; k < E_RBF; k++) {
                float r = rbf[k];
                fw0 += r * s_Fw[k * F3H + j];
                fw1 += r * s_Fw[k * F3H + H + j];
                fw2 += r * s_Fw[k * F3H + 2 * H + j];
            }
            const float* so = g_so + (size_t)src * F3H;
            float gsv = fw0 * fcut * so[j];
            float gev = fw1 * fcut * so[H + j];
            float ms  = fw2 * fcut * so[2 * H + j];

            const float* vin = g_vecA + (size_t)src * 3 * H;
            accs += ms;
            av0 += vin[j]         * gsv + gev * u0;
            av1 += vin[H + j]     * gsv + gev * u1;
            av2 += vin[2 * H + j] * gsv + gev * u2;
        }
        g_ns2[(size_t)n * H + j] = g_ns[(size_t)n * H + j] + accs;
        float* vo = g_vecB + (size_t)n * 3 * H;
        const float* va = g_vecA + (size_t)n * 3 * H;
        vo[j]         = va[j]         + av0;
        vo[H + j]     = va[H + j]     + av1;
        vo[2 * H + j] = va[2 * H + j] + av2;
    }
}

// ---------- update block: reads g_ns2/g_vecB, writes g_ns/g_vecA ----------
__global__ void __launch_bounds__(H) k_update(const float* __restrict__ Uw,
                                              const float* __restrict__ Ub,
                                              const float* __restrict__ Vw,
                                              const float* __restrict__ Vb,
                                              const float* __restrict__ W1,
                                              const float* __restrict__ b1,
                                              const float* __restrict__ W2,
                                              const float* __restrict__ b2) {
    int i0 = blockIdx.x * NPU, j = threadIdx.x;
    __shared__ float s_v[NPU][3 * H];
    __shared__ float s_in[NPU][2 * H];
    __shared__ float s_h[NPU][H];

    float ns[NPU];
#pragma unroll
    for (int n = 0; n < NPU; n++) {
#pragma unroll
        for (int d = 0; d < 3; d++)
            s_v[n][d * H + j] = g_vecB[(i0 + n) * 3 * H + d * H + j];
        ns[n] = g_ns2[(i0 + n) * H + j];
        s_in[n][H + j] = ns[n];
    }
    __syncthreads();

    float Uv[NPU][3], Vv[NPU][3];
    float ub = Ub[j], vb = Vb[j];
#pragma unroll
    for (int n = 0; n < NPU; n++)
#pragma unroll
        for (int d = 0; d < 3; d++) { Uv[n][d] = ub; Vv[n][d] = vb; }

    for (int k = 0; k < H; k++) {
        float u = Uw[k * H + j];
        float v = Vw[k * H + j];
#pragma unroll
        for (int n = 0; n < NPU; n++)
#pragma unroll
            for (int d = 0; d < 3; d++) {
                float x = s_v[n][d * H + k];
                Uv[n][d] += x * u;
                Vv[n][d] += x * v;
            }
    }
#pragma unroll
    for (int n = 0; n < NPU; n++)
        s_in[n][j] = sqrtf(Vv[n][0] * Vv[n][0] + Vv[n][1] * Vv[n][1] + Vv[n][2] * Vv[n][2]);
    __syncthreads();

    float acc[NPU];
    float bb = b1[j];
#pragma unroll
    for (int n = 0; n < NPU; n++) acc[n] = bb;
    for (int k = 0; k < 2 * H; k++) {
        float w = W1[k * H + j];
#pragma unroll
        for (int n = 0; n < NPU; n++) acc[n] += s_in[n][k] * w;
    }
#pragma unroll
    for (int n = 0; n < NPU; n++) s_h[n][j] = silu_f(acc[n]);
    __syncthreads();

    float a0[NPU], a1[NPU], a2[NPU];
    float c0 = b2[j], c1 = b2[H + j], c2 = b2[2 * H + j];
#pragma unroll
    for (int n = 0; n < NPU; n++) { a0[n] = c0; a1[n] = c1; a2[n] = c2; }
    for (int k = 0; k < H; k++) {
        float w0 = W2[k * F3H + j];
        float w1 = W2[k * F3H + H + j];
        float w2 = W2[k * F3H + 2 * H + j];
#pragma unroll
        for (int n = 0; n < NPU; n++) {
            float h = s_h[n][k];
            a0[n] += h * w0; a1[n] += h * w1; a2[n] += h * w2;
        }
    }
#pragma unroll
    for (int n = 0; n < NPU; n++) {
        float dot = 0.0f;
#pragma unroll
        for (int d = 0; d < 3; d++) {
            g_vecA[(i0 + n) * 3 * H + d * H + j] = s_v[n][d * H + j] + a0[n] * Uv[n][d];
            dot += Uv[n][d] * Vv[n][d];
        }
        g_ns[(i0 + n) * H + j] = ns[n] + a1[n] * dot + a2[n];
    }
}

// ---------- readout ----------
__global__ void __launch_bounds__(H) k_readout(const float* __restrict__ W1,
                                               const float* __restrict__ b1,
                                               const float* __restrict__ W2,
                                               const float* __restrict__ b2,
                                               float* __restrict__ out) {
    int i0 = blockIdx.x * NPB, j = threadIdx.x;
    __shared__ float s_x[NPB][H];
    __shared__ float s_h[NPB][H];
#pragma unroll
    for (int n = 0; n < NPB; n++) s_x[n][j] = g_ns[(i0 + n) * H + j];
    __syncthreads();

    float acc[NPB];
    float bb = b1[j];
#pragma unroll
    for (int n = 0; n < NPB; n++) acc[n] = bb;
    for (int k = 0; k < H; k++) {
        float w = W1[k * H + j];
#pragma unroll
        for (int n = 0; n < NPB; n++) acc[n] += s_x[n][k] * w;
    }
#pragma unroll
    for (int n = 0; n < NPB; n++) s_h[n][j] = silu_f(acc[n]);
    __syncthreads();

    float a[NPB];
    float c = b2[j];
#pragma unroll
    for (int n = 0; n < NPB; n++) a[n] = c;
    for (int k = 0; k < H; k++) {
        float w = W2[k * H + j];
#pragma unroll
        for (int n = 0; n < NPB; n++) a[n] += s_h[n][k] * w;
    }
#pragma unroll
    for (int n = 0; n < NPB; n++) out[(i0 + n) * H + j] = a[n];
}

// ---------- host launcher ----------
extern "C" void kernel_launch(void* const* d_in, const int* in_sizes, int n_in,
                              void* d_out, int out_size) {
    const int*   z      = (const int*)  d_in[0];
    const int*   edge   = (const int*)  d_in[1];
    const float* ediff  = (const float*)d_in[2];
    const float* edist  = (const float*)d_in[3];
    const float* embed  = (const float*)d_in[4];
    const float* mfw    = (const float*)d_in[5];
    const float* mfb    = (const float*)d_in[6];
    const float* mw1    = (const float*)d_in[7];
    const float* mb1    = (const float*)d_in[8];
    const float* mw2    = (const float*)d_in[9];
    const float* mb2    = (const float*)d_in[10];
    const float* uUw    = (const float*)d_in[11];
    const float* uUb    = (const float*)d_in[12];
    const float* uVw    = (const float*)d_in[13];
    const float* uVb    = (const float*)d_in[14];
    const float* uw1    = (const float*)d_in[15];
    const float* ub1    = (const float*)d_in[16];
    const float* uw2    = (const float*)d_in[17];
    const float* ub2    = (const float*)d_in[18];
    const float* row1   = (const float*)d_in[19];
    const float* rob1   = (const float*)d_in[20];
    const float* row2   = (const float*)d_in[21];
    const float* rob2   = (const float*)d_in[22];
    float* out = (float*)d_out;

    // CSR build (once per launch)
    k_zero_cnt<<<(N_NODES + 255) / 256, 256>>>();
    k_hist<<<(N_EDGES + 255) / 256, 256>>>(edge);
    k_scan<<<1, 1024>>>();
    k_scatter<<<(N_EDGES + 255) / 256, 256>>>(edge, ediff, edist);

    k_init<<<N_NODES, H>>>(z, embed);

    for (int l = 0; l < L_LAYERS; l++) {
        k_scalar_out<<<N_NODES / NPB, H>>>(mw1 + l * H * H, mb1 + l * H,
                                           mw2 + l * H * F3H, mb2 + l * F3H);
        k_aggregate<<<N_NODES / NGB, H>>>(mfw + l * E_RBF * F3H, mfb + l * F3H);
        k_update<<<N_NODES / NPU, H>>>(uUw + l * H * H, uUb + l * H,
                                       uVw + l * H * H, uVb + l * H,
                                       uw1 + l * 2 * H * H, ub1 + l * H,
                                       uw2 + l * H * F3H, ub2 + l * F3H);
    }
    k_readout<<<N_NODES / NPB, H>>>(row1, rob1, row2, rob2, out);
}

// round 8
// speedup vs baseline: 2.8670x; 1.1115x over previous
#include <cuda_runtime.h>
#include <math.h>

#define N_NODES 10000
#define N_EDGES 160000
#define H       128
#define F3H     384
#define E_RBF   20
#define L_LAYERS 3
#define PI_F    3.14159265358979f
#define CUTOFF_F 5.0f

#define NPB 4     // nodes per block (scalar_out / readout)
#define NPU 4     // nodes per block (update)
#define NGB 4     // nodes per block (aggregate)

// ---------- persistent scratch ----------
__device__ float g_ns  [N_NODES * H];
__device__ float g_ns2 [N_NODES * H];
__device__ float g_vecA[N_NODES * 3 * H];
__device__ float g_vecB[N_NODES * 3 * H];
__device__ float g_so  [N_NODES * F3H];

// CSR / sorted edge data (built once per launch)
__device__ int    g_rowptr[N_NODES + 1];
__device__ int    g_cursor[N_NODES];
__device__ int    g_src_s [N_EDGES];
__device__ float4 g_geo_s [N_EDGES];             // {fcut, u0, u1, u2}
__device__ float  g_rbf_s [N_EDGES * E_RBF];     // 80 B per edge, 16B-aligned

__device__ __forceinline__ float silu_f(float x) {
    return x / (1.0f + expf(-x));
}

// ---------- CSR build ----------
__global__ void k_zero_cnt() {
    int i = blockIdx.x * blockDim.x + threadIdx.x;
    if (i < N_NODES) g_cursor[i] = 0;
}

__global__ void k_hist(const int* __restrict__ edge) {
    int e = blockIdx.x * blockDim.x + threadIdx.x;
    if (e < N_EDGES) atomicAdd(&g_cursor[edge[2 * e]], 1);
}

__global__ void __launch_bounds__(1024) k_scan() {
    __shared__ int s_part[1024];
    int tid = threadIdx.x;
    const int CH = 10;
    int base = tid * CH;
    int local[CH];
    int sum = 0;
#pragma unroll
    for (int i = 0; i < CH; i++) {
        int idx = base + i;
        int v = (idx < N_NODES) ? g_cursor[idx] : 0;
        local[i] = sum;
        sum += v;
    }
    s_part[tid] = sum;
    __syncthreads();
    for (int off = 1; off < 1024; off <<= 1) {
        int add = (tid >= off) ? s_part[tid - off] : 0;
        __syncthreads();
        s_part[tid] += add;
        __syncthreads();
    }
    int excl = (tid > 0) ? s_part[tid - 1] : 0;
#pragma unroll
    for (int i = 0; i < CH; i++) {
        int idx = base + i;
        if (idx < N_NODES) {
            int rp = excl + local[i];
            g_rowptr[idx] = rp;
            g_cursor[idx] = rp;
        }
    }
    if (tid == 0) g_rowptr[N_NODES] = N_EDGES;
}

__global__ void k_scatter(const int* __restrict__ edge,
                          const float* __restrict__ ediff,
                          const float* __restrict__ edist) {
    int e = blockIdx.x * blockDim.x + threadIdx.x;
    if (e >= N_EDGES) return;
    int dst = edge[2 * e], src = edge[2 * e + 1];
    int pos = atomicAdd(&g_cursor[dst], 1);
    g_src_s[pos] = src;
    float dist = edist[e];
    float fcut = (dist < CUTOFF_F) ? 0.5f * (cosf(PI_F * dist / CUTOFF_F) + 1.0f) : 0.0f;
    float inv = 1.0f / dist;
    float4 geo;
    geo.x = fcut;
    geo.y = ediff[3 * e + 0] * inv;
    geo.z = ediff[3 * e + 1] * inv;
    geo.w = ediff[3 * e + 2] * inv;
    g_geo_s[pos] = geo;
    float4* rb4 = reinterpret_cast<float4*>(g_rbf_s + (size_t)pos * E_RBF);
#pragma unroll
    for (int q = 0; q < E_RBF / 4; q++) {
        float4 v;
        v.x = sinf(dist * (float)(4 * q + 1) * (PI_F / CUTOFF_F)) * inv;
        v.y = sinf(dist * (float)(4 * q + 2) * (PI_F / CUTOFF_F)) * inv;
        v.z = sinf(dist * (float)(4 * q + 3) * (PI_F / CUTOFF_F)) * inv;
        v.w = sinf(dist * (float)(4 * q + 4) * (PI_F / CUTOFF_F)) * inv;
        rb4[q] = v;
    }
}

// ---------- init ----------
__global__ void __launch_bounds__(H) k_init(const int* __restrict__ z,
                                            const float* __restrict__ embed) {
    int i = blockIdx.x, j = threadIdx.x;
    g_ns[i * H + j] = embed[z[i] * H + j];
#pragma unroll
    for (int d = 0; d < 3; d++) g_vecA[i * 3 * H + d * H + j] = 0.0f;
}

// ---------- scalar_out ----------
__global__ void __launch_bounds__(H) k_scalar_out(const float* __restrict__ W1,
                                                  const float* __restrict__ b1,
                                                  const float* __restrict__ W2,
                                                  const float* __restrict__ b2) {
    int i0 = blockIdx.x * NPB, j = threadIdx.x;
    __shared__ float s_x[NPB][H];
    __shared__ float s_h[NPB][H];
#pragma unroll
    for (int n = 0; n < NPB; n++) s_x[n][j] = g_ns[(i0 + n) * H + j];
    __syncthreads();

    float acc[NPB];
    float bb = b1[j];
#pragma unroll
    for (int n = 0; n < NPB; n++) acc[n] = bb;
    for (int k = 0; k < H; k++) {
        float w = W1[k * H + j];
#pragma unroll
        for (int n = 0; n < NPB; n++) acc[n] += s_x[n][k] * w;
    }
#pragma unroll
    for (int n = 0; n < NPB; n++) s_h[n][j] = silu_f(acc[n]);
    __syncthreads();

    float a0[NPB], a1[NPB], a2[NPB];
    float c0 = b2[j], c1 = b2[H + j], c2 = b2[2 * H + j];
#pragma unroll
    for (int n = 0; n < NPB; n++) { a0[n] = c0; a1[n] = c1; a2[n] = c2; }
    for (int k = 0; k < H; k++) {
        float w0 = W2[k * F3H + j];
        float w1 = W2[k * F3H + H + j];
        float w2 = W2[k * F3H + 2 * H + j];
#pragma unroll
        for (int n = 0; n < NPB; n++) {
            float h = s_h[n][k];
            a0[n] += h * w0; a1[n] += h * w1; a2[n] += h * w2;
        }
    }
#pragma unroll
    for (int n = 0; n < NPB; n++) {
        g_so[(i0 + n) * F3H + j]         = a0[n];
        g_so[(i0 + n) * F3H + H + j]     = a1[n];
        g_so[(i0 + n) * F3H + 2 * H + j] = a2[n];
    }
}

// ---------- aggregate v2: filter weights in registers, no smem ----------
__global__ void __launch_bounds__(H) k_aggregate(const float* __restrict__ Fw,
                                                 const float* __restrict__ Fb) {
    int j = threadIdx.x;

    // per-thread column slice of the filter weights (once per block)
    float rw0[E_RBF], rw1[E_RBF], rw2[E_RBF];
#pragma unroll
    for (int k = 0; k < E_RBF; k++) {
        rw0[k] = Fw[k * F3H + j];
        rw1[k] = Fw[k * F3H + H + j];
        rw2[k] = Fw[k * F3H + 2 * H + j];
    }
    float rb0 = Fb[j], rb1 = Fb[H + j], rb2 = Fb[2 * H + j];

    int n0 = blockIdx.x * NGB;
    for (int n = n0; n < n0 + NGB; n++) {
        int r0 = g_rowptr[n], r1 = g_rowptr[n + 1];
        float accs = 0.0f, av0 = 0.0f, av1 = 0.0f, av2 = 0.0f;
#pragma unroll 2
        for (int p = r0; p < r1; p++) {
            int src = g_src_s[p];
            float4 geo = g_geo_s[p];              // {fcut, u0, u1, u2}
            const float4* rbf4 = reinterpret_cast<const float4*>(g_rbf_s + (size_t)p * E_RBF);
            float4 rA = rbf4[0], rB = rbf4[1], rC = rbf4[2], rD = rbf4[3], rE = rbf4[4];
            float rbf[E_RBF] = {rA.x, rA.y, rA.z, rA.w, rB.x, rB.y, rB.z, rB.w,
                                rC.x, rC.y, rC.z, rC.w, rD.x, rD.y, rD.z, rD.w,
                                rE.x, rE.y, rE.z, rE.w};

            float fw0 = rb0, fw1 = rb1, fw2 = rb2;
#pragma unroll
            for (int k = 0; k < E_RBF; k++) {
                fw0 += rbf[k] * rw0[k];
                fw1 += rbf[k] * rw1[k];
                fw2 += rbf[k] * rw2[k];
            }

            const float* so = g_so + (size_t)src * F3H;
            float fcut = geo.x;
            float gsv = fw0 * (fcut * so[j]);
            float gev = fw1 * (fcut * so[H + j]);
            accs += fw2 * (fcut * so[2 * H + j]);

            const float* vin = g_vecA + (size_t)src * 3 * H;
            av0 += vin[j]         * gsv + gev * geo.y;
            av1 += vin[H + j]     * gsv + gev * geo.z;
            av2 += vin[2 * H + j] * gsv + gev * geo.w;
        }
        g_ns2[(size_t)n * H + j] = g_ns[(size_t)n * H + j] + accs;
        float* vo = g_vecB + (size_t)n * 3 * H;
        const float* va = g_vecA + (size_t)n * 3 * H;
        vo[j]         = va[j]         + av0;
        vo[H + j]     = va[H + j]     + av1;
        vo[2 * H + j] = va[2 * H + j] + av2;
    }
}

// ---------- update ----------
__global__ void __launch_bounds__(H) k_update(const float* __restrict__ Uw,
                                              const float* __restrict__ Ub,
                                              const float* __restrict__ Vw,
                                              const float* __restrict__ Vb,
                                              const float* __restrict__ W1,
                                              const float* __restrict__ b1,
                                              const float* __restrict__ W2,
                                              const float* __restrict__ b2) {
    int i0 = blockIdx.x * NPU, j = threadIdx.x;
    __shared__ float s_v[NPU][3 * H];
    __shared__ float s_in[NPU][2 * H];
    __shared__ float s_h[NPU][H];

    float ns[NPU];
#pragma unroll
    for (int n = 0; n < NPU; n++) {
#pragma unroll
        for (int d = 0; d < 3; d++)
            s_v[n][d * H + j] = g_vecB[(i0 + n) * 3 * H + d * H + j];
        ns[n] = g_ns2[(i0 + n) * H + j];
        s_in[n][H + j] = ns[n];
    }
    __syncthreads();

    float Uv[NPU][3], Vv[NPU][3];
    float ub = Ub[j], vb = Vb[j];
#pragma unroll
    for (int n = 0; n < NPU; n++)
#pragma unroll
        for (int d = 0; d < 3; d++) { Uv[n][d] = ub; Vv[n][d] = vb; }

    for (int k = 0; k < H; k++) {
        float u = Uw[k * H + j];
        float v = Vw[k * H + j];
#pragma unroll
        for (int n = 0; n < NPU; n++)
#pragma unroll
            for (int d = 0; d < 3; d++) {
                float x = s_v[n][d * H + k];
                Uv[n][d] += x * u;
                Vv[n][d] += x * v;
            }
    }
#pragma unroll
    for (int n = 0; n < NPU; n++)
        s_in[n][j] = sqrtf(Vv[n][0] * Vv[n][0] + Vv[n][1] * Vv[n][1] + Vv[n][2] * Vv[n][2]);
    __syncthreads();

    float acc[NPU];
    float bb = b1[j];
#pragma unroll
    for (int n = 0; n < NPU; n++) acc[n] = bb;
    for (int k = 0; k < 2 * H; k++) {
        float w = W1[k * H + j];
#pragma unroll
        for (int n = 0; n < NPU; n++) acc[n] += s_in[n][k] * w;
    }
#pragma unroll
    for (int n = 0; n < NPU; n++) s_h[n][j] = silu_f(acc[n]);
    __syncthreads();

    float a0[NPU], a1[NPU], a2[NPU];
    float c0 = b2[j], c1 = b2[H + j], c2 = b2[2 * H + j];
#pragma unroll
    for (int n = 0; n < NPU; n++) { a0[n] = c0; a1[n] = c1; a2[n] = c2; }
    for (int k = 0; k < H; k++) {
        float w0 = W2[k * F3H + j];
        float w1 = W2[k * F3H + H + j];
        float w2 = W2[k * F3H + 2 * H + j];
#pragma unroll
        for (int n = 0; n < NPU; n++) {
            float h = s_h[n][k];
            a0[n] += h * w0; a1[n] += h * w1; a2[n] += h * w2;
        }
    }
#pragma unroll
    for (int n = 0; n < NPU; n++) {
        float dot = 0.0f;
#pragma unroll
        for (int d = 0; d < 3; d++) {
            g_vecA[(i0 + n) * 3 * H + d * H + j] = s_v[n][d * H + j] + a0[n] * Uv[n][d];
            dot += Uv[n][d] * Vv[n][d];
        }
        g_ns[(i0 + n) * H + j] = ns[n] + a1[n] * dot + a2[n];
    }
}

// ---------- readout ----------
__global__ void __launch_bounds__(H) k_readout(const float* __restrict__ W1,
                                               const float* __restrict__ b1,
                                               const float* __restrict__ W2,
                                               const float* __restrict__ b2,
                                               float* __restrict__ out) {
    int i0 = blockIdx.x * NPB, j = threadIdx.x;
    __shared__ float s_x[NPB][H];
    __shared__ float s_h[NPB][H];
#pragma unroll
    for (int n = 0; n < NPB; n++) s_x[n][j] = g_ns[(i0 + n) * H + j];
    __syncthreads();

    float acc[NPB];
    float bb = b1[j];
#pragma unroll
    for (int n = 0; n < NPB; n++) acc[n] = bb;
    for (int k = 0; k < H; k++) {
        float w = W1[k * H + j];
#pragma unroll
        for (int n = 0; n < NPB; n++) acc[n] += s_x[n][k] * w;
    }
#pragma unroll
    for (int n = 0; n < NPB; n++) s_h[n][j] = silu_f(acc[n]);
    __syncthreads();

    float a[NPB];
    float c = b2[j];
#pragma unroll
    for (int n = 0; n < NPB; n++) a[n] = c;
    for (int k = 0; k < H; k++) {
        float w = W2[k * H + j];
#pragma unroll
        for (int n = 0; n < NPB; n++) a[n] += s_h[n][k] * w;
    }
#pragma unroll
    for (int n = 0; n < NPB; n++) out[(i0 + n) * H + j] = a[n];
}

// ---------- host launcher ----------
extern "C" void kernel_launch(void* const* d_in, const int* in_sizes, int n_in,
                              void* d_out, int out_size) {
    const int*   z      = (const int*)  d_in[0];
    const int*   edge   = (const int*)  d_in[1];
    const float* ediff  = (const float*)d_in[2];
    const float* edist  = (const float*)d_in[3];
    const float* embed  = (const float*)d_in[4];
    const float* mfw    = (const float*)d_in[5];
    const float* mfb    = (const float*)d_in[6];
    const float* mw1    = (const float*)d_in[7];
    const float* mb1    = (const float*)d_in[8];
    const float* mw2    = (const float*)d_in[9];
    const float* mb2    = (const float*)d_in[10];
    const float* uUw    = (const float*)d_in[11];
    const float* uUb    = (const float*)d_in[12];
    const float* uVw    = (const float*)d_in[13];
    const float* uVb    = (const float*)d_in[14];
    const float* uw1    = (const float*)d_in[15];
    const float* ub1    = (const float*)d_in[16];
    const float* uw2    = (const float*)d_in[17];
    const float* ub2    = (const float*)d_in[18];
    const float* row1   = (const float*)d_in[19];
    const float* rob1   = (const float*)d_in[20];
    const float* row2   = (const float*)d_in[21];
    const float* rob2   = (const float*)d_in[22];
    float* out = (float*)d_out;

    k_zero_cnt<<<(N_NODES + 255) / 256, 256>>>();
    k_hist<<<(N_EDGES + 255) / 256, 256>>>(edge);
    k_scan<<<1, 1024>>>();
    k_scatter<<<(N_EDGES + 255) / 256, 256>>>(edge, ediff, edist);

    k_init<<<N_NODES, H>>>(z, embed);

    for (int l = 0; l < L_LAYERS; l++) {
        k_scalar_out<<<N_NODES / NPB, H>>>(mw1 + l * H * H, mb1 + l * H,
                                           mw2 + l * H * F3H, mb2 + l * F3H);
        k_aggregate<<<N_NODES / NGB, H>>>(mfw + l * E_RBF * F3H, mfb + l * F3H);
        k_update<<<N_NODES / NPU, H>>>(uUw + l * H * H, uUb + l * H,
                                       uVw + l * H * H, uVb + l * H,
                                       uw1 + l * 2 * H * H, ub1 + l * H,
                                       uw2 + l * H * F3H, ub2 + l * F3H);
    }
    k_readout<<<N_NODES / NPB, H>>>(row1, rob1, row2, rob2, out);
}